// round 14
// baseline (speedup 1.0000x reference)
#include <cuda_runtime.h>
#include <cuda_bf16.h>

#define PI_D 3.14159265358979323846
#define PI_F 3.14159265358979f
#define DNUM 729
#define DPAD 732
#define ANUM 180
#define HNUM 512
#define WNUM 512
#define NPIX (HNUM * WNUM)
#define BNUM 2
#define CHUNK 244
#define EXTLO 32            /* rows below u=0 */
#define EXTROWS 241         /* u in [-32, 207] = 240 rows, +1 for angle 179 */
#define ROW179 240          /* storage row of leftover angle 179 */
#define NBLK 1024           /* persistent grid size (<= 148*8 residency) */

// ================= compile-time tables =================
constexpr double CT_PI = 3.14159265358979323846;

constexpr double ct_cos(double x) {
    while (x > CT_PI) x -= 2.0 * CT_PI;
    while (x < -CT_PI) x += 2.0 * CT_PI;
    double x2 = x * x;
    double term = 1.0, sum = 1.0;
    for (int i = 1; i <= 15; ++i) {
        term *= -x2 / (double)((2 * i - 1) * (2 * i));
        sum += term;
    }
    return sum;
}

constexpr float ct_h(int j) {
    double acc = 0.0;
    for (int k = 1; k < 729; k += 2) {
        int r = (k * j) % 729;
        acc += (-1.0 / (CT_PI * CT_PI * (double)k * (double)k))
             * ct_cos((double)r * (2.0 * CT_PI / 729.0));
    }
    return (float)((0.25 + acc) / 729.0);
}
constexpr float ct_cosa(int j) { return (float)ct_cos((double)j * (CT_PI / 179.0)); }
constexpr float ct_sina(int j) { return (float)ct_cos((double)j * (CT_PI / 179.0) - CT_PI * 0.5); }

#define R1(f, n) f(n)
#define R4(f, n) R1(f, n), R1(f, n + 1), R1(f, n + 2), R1(f, n + 3)
#define R16(f, n) R4(f, n), R4(f, n + 4), R4(f, n + 8), R4(f, n + 12)
#define R64(f, n) R16(f, n), R16(f, n + 16), R16(f, n + 32), R16(f, n + 48)
#define R256(f, n) R64(f, n), R64(f, n + 64), R64(f, n + 128), R64(f, n + 192)

__device__ const float g_h_tab[DNUM] = {
    R256(ct_h, 0), R256(ct_h, 256), R64(ct_h, 512), R64(ct_h, 576),
    R64(ct_h, 640), R16(ct_h, 704), R4(ct_h, 720), R4(ct_h, 724), R1(ct_h, 728)
};
__device__ const float g_cos_tab[ANUM] = {
    R64(ct_cosa, 0), R64(ct_cosa, 64), R16(ct_cosa, 128),
    R16(ct_cosa, 144), R16(ct_cosa, 160), R4(ct_cosa, 176)
};
__device__ const float g_sin_tab[ANUM] = {
    R64(ct_sina, 0), R64(ct_sina, 64), R16(ct_sina, 128),
    R16(ct_sina, 144), R16(ct_sina, 160), R4(ct_sina, 176)
};

// ---------------- device scratch ----------------
__device__ float g_filt_ext[BNUM * EXTROWS * DPAD];
__device__ unsigned int g_bar;     // monotonic ticket barrier (replay-safe)

// ---------------- f32x2 helpers ----------------
__device__ __forceinline__ unsigned long long dup2(float f) {
    unsigned long long r;
    asm("mov.b64 %0, {%1, %1};" : "=l"(r) : "f"(f));
    return r;
}
__device__ __forceinline__ void ffma2(unsigned long long& d,
                                      unsigned long long a,
                                      unsigned long long b) {
    asm("fma.rn.f32x2 %0, %1, %2, %0;" : "+l"(d) : "l"(a), "l"(b));
}
__device__ __forceinline__ void fadd2(unsigned long long& d, unsigned long long a) {
    asm("add.rn.f32x2 %0, %0, %1;" : "+l"(d) : "l"(a));
}
__device__ __forceinline__ void unpack2(unsigned long long v, float& lo, float& hi) {
    asm("mov.b64 {%0, %1}, %2;" : "=f"(lo), "=f"(hi) : "l"(v));
}

// ============================================================
// Single persistent kernel: filter phase -> barrier -> backproject phase
// ============================================================
__global__ void __launch_bounds__(128, 8)
fbp_fused_kernel(const float* __restrict__ sino, float* __restrict__ out) {
    // ---- filter-phase smem ----
    __shared__ __align__(16) float2 s2[736];
    __shared__ __align__(16) float s_h[1472];
    __shared__ __align__(16) unsigned long long s_part[4][64];
    // ---- backproject-phase smem ----
    __shared__ __align__(8) float2 s_cs[EXTROWS];
    __shared__ float p0s[BNUM][ANUM], p728s[BNUM][ANUM];

    int tid = threadIdx.x;
    int blk = blockIdx.x;

    // ================= phase 1: filter (blocks 0..539) =================
    if (blk < 540) {
        int a = blk / 3;
        int chunk = blk - 3 * a;
        const float* r0 = sino + a * DNUM;
        const float* r1 = sino + (ANUM + a) * DNUM;
        for (int i = tid; i < 736; i += 128) {
            float v0 = (i < DNUM) ? __ldg(r0 + i) : 0.0f;
            float v1 = (i < DNUM) ? __ldg(r1 + i) : 0.0f;
            s2[i] = make_float2(v0, v1);
        }
        for (int i = tid; i < 1472; i += 128) {
            int j = i - 6;
            if (j < 0) j += 729;
            if (j >= 729) j -= 729;
            if (j >= 729) j -= 729;
            s_h[i] = g_h_tab[j];
        }
        __syncthreads();

        int half = tid >> 6;
        int t = tid & 63;
        unsigned long long ac0 = 0ull, ac1 = 0ull, ac2 = 0ull, ac3 = 0ull;
        if (t < 61) {
            int n0 = chunk * CHUNK + 4 * t;
            const double* sd = reinterpret_cast<const double*>(s2);
            int g0 = half ? 46 : 0;
            int g1 = half ? 92 : 46;
            #pragma unroll 2
            for (int g = g0; g < g1; ++g) {
                int m0 = 8 * g;
                double2 sA = *reinterpret_cast<const double2*>(sd + m0);
                double2 sB = *reinterpret_cast<const double2*>(sd + m0 + 2);
                double2 sC = *reinterpret_cast<const double2*>(sd + m0 + 4);
                double2 sD = *reinterpret_cast<const double2*>(sd + m0 + 6);
                unsigned long long k0 = __double_as_longlong(sA.x);
                unsigned long long k1 = __double_as_longlong(sA.y);
                unsigned long long k2 = __double_as_longlong(sB.x);
                unsigned long long k3 = __double_as_longlong(sB.y);
                unsigned long long k4 = __double_as_longlong(sC.x);
                unsigned long long k5 = __double_as_longlong(sC.y);
                unsigned long long k6 = __double_as_longlong(sD.x);
                unsigned long long k7 = __double_as_longlong(sD.y);
                int L = n0 - m0 + 728;
                float4 h0 = *reinterpret_cast<const float4*>(s_h + L);
                float4 h1 = *reinterpret_cast<const float4*>(s_h + L + 4);
                float4 h2 = *reinterpret_cast<const float4*>(s_h + L + 8);
                unsigned long long H0 = dup2(h0.x), H1 = dup2(h0.y);
                unsigned long long H2 = dup2(h0.z), H3 = dup2(h0.w);
                unsigned long long H4 = dup2(h1.x), H5 = dup2(h1.y);
                unsigned long long H6 = dup2(h1.z), H7 = dup2(h1.w);
                unsigned long long H8 = dup2(h2.x), H9 = dup2(h2.y);
                unsigned long long H10 = dup2(h2.z);
                ffma2(ac0, k0, H7);  ffma2(ac1, k0, H8);  ffma2(ac2, k0, H9);  ffma2(ac3, k0, H10);
                ffma2(ac0, k1, H6);  ffma2(ac1, k1, H7);  ffma2(ac2, k1, H8);  ffma2(ac3, k1, H9);
                ffma2(ac0, k2, H5);  ffma2(ac1, k2, H6);  ffma2(ac2, k2, H7);  ffma2(ac3, k2, H8);
                ffma2(ac0, k3, H4);  ffma2(ac1, k3, H5);  ffma2(ac2, k3, H6);  ffma2(ac3, k3, H7);
                ffma2(ac0, k4, H3);  ffma2(ac1, k4, H4);  ffma2(ac2, k4, H5);  ffma2(ac3, k4, H6);
                ffma2(ac0, k5, H2);  ffma2(ac1, k5, H3);  ffma2(ac2, k5, H4);  ffma2(ac3, k5, H5);
                ffma2(ac0, k6, H1);  ffma2(ac1, k6, H2);  ffma2(ac2, k6, H3);  ffma2(ac3, k6, H4);
                ffma2(ac0, k7, H0);  ffma2(ac1, k7, H1);  ffma2(ac2, k7, H2);  ffma2(ac3, k7, H3);
            }
            if (half) {
                s_part[0][t] = ac0;
                s_part[1][t] = ac1;
                s_part[2][t] = ac2;
                s_part[3][t] = ac3;
            }
        }
        __syncthreads();

        if (!half && t < 61) {
            fadd2(ac0, s_part[0][t]);
            fadd2(ac1, s_part[1][t]);
            fadd2(ac2, s_part[2][t]);
            fadd2(ac3, s_part[3][t]);
            int n0 = chunk * CHUNK + 4 * t;
            float o00, o01, o02, o03, o10, o11, o12, o13;
            unpack2(ac0, o00, o10);
            unpack2(ac1, o01, o11);
            unpack2(ac2, o02, o12);
            unpack2(ac3, o03, o13);
            float4 q0 = make_float4(o00, o01, o02, o03);
            float4 q1 = make_float4(o10, o11, o12, o13);
            int rowc = (a == 179) ? ROW179 : a + EXTLO;
            *reinterpret_cast<float4*>(g_filt_ext + rowc * DPAD + n0) = q0;
            *reinterpret_cast<float4*>(g_filt_ext + (EXTROWS + rowc) * DPAD + n0) = q1;
            if (a <= 28) {
                int r2 = a + 179 + EXTLO;
                *reinterpret_cast<float4*>(g_filt_ext + r2 * DPAD + n0) = q0;
                *reinterpret_cast<float4*>(g_filt_ext + (EXTROWS + r2) * DPAD + n0) = q1;
            }
            if (a >= 147 && a <= 178) {
                int r3 = a - 179 + EXTLO;
                *reinterpret_cast<float4*>(g_filt_ext + r3 * DPAD + n0) = q0;
                *reinterpret_cast<float4*>(g_filt_ext + (EXTROWS + r3) * DPAD + n0) = q1;
            }
        }
    }

    // ================= device-wide barrier (monotonic ticket) ============
    __syncthreads();
    if (tid == 0) {
        __threadfence();
        unsigned tk = atomicAdd(&g_bar, 1u);
        unsigned target = (tk / NBLK + 1u) * NBLK;
        while (*((volatile unsigned*)&g_bar) < target) __nanosleep(100);
        __threadfence();
    }
    __syncthreads();

    // ================= phase 2: backprojection ==========================
    const float KIDX = (float)(729.0 / (2.0 * PI_D));
    for (int e = tid; e < EXTROWS; e += 128) {
        int a;
        if (e == ROW179) a = 179;
        else {
            a = e - EXTLO;
            if (a < 0) a += 179;
            if (a > 178) a -= 179;
        }
        s_cs[e] = make_float2(g_cos_tab[a] * KIDX, g_sin_tab[a] * KIDX);
    }
    {   // 4 warps: prefix scans for (b, col) = (w>>1, w&1)
        int w = tid >> 5;
        int l = tid & 31;
        int bb = w >> 1;
        const float* base = g_filt_ext + (bb * EXTROWS + EXTLO) * DPAD + ((w & 1) ? 728 : 0);
        float* outp = (w & 1) ? p728s[bb] : p0s[bb];
        float carry = 0.0f;
        #pragma unroll
        for (int c = 0; c < 6; ++c) {
            int a = c * 32 + l;
            float v = (a < 179) ? base[a * DPAD] : 0.0f;
            float s = v;
            #pragma unroll
            for (int off = 1; off < 32; off <<= 1) {
                float t = __shfl_up_sync(0xffffffffu, s, off);
                if (l >= off) s += t;
            }
            if (a < ANUM) outp[a] = carry + s - v;    // exclusive prefix
            carry += __shfl_sync(0xffffffffu, s, 31);
        }
    }
    __syncthreads();
    const float2* __restrict__ csx = s_cs + EXTLO;

    // 4 tiles of 128 pixels: t = blk + k*1024 pairs row y with row y+256
    #pragma unroll 1
    for (int k = 0; k < 4; ++k) {
        int t = blk + (k << 10);
        int b = t >> 11;
        int p = ((t & 2047) << 7) | tid;
        int y = p >> 9;
        int x = p & 511;
        float xc = (float)x - 256.0f;
        float yc = (float)y - 256.0f;
        const float* __restrict__ fbx = g_filt_ext + b * (EXTROWS * DPAD) + EXTLO * DPAD;
        const float* pp0 = p0s[b];
        const float* pp728 = p728s[b];

        float d2 = xc * xc + yc * yc;
        int lo, hi, acfl = 0;
        if (d2 < 256.0f) {
            lo = 0; hi = 178;
        } else {
            // fast atan2(-xc, yc) -> acf in [0, 179); err <= ~0.09 steps
            float u = -xc, v = yc;
            float ax = fabsf(u), av = fabsf(v);
            float z = __fdividef(fminf(ax, av), fmaxf(ax, av));
            float z2 = z * z;
            float tt = z * fmaf(z2, fmaf(z2, 0.0793313f, -0.2886790f), 0.9953540f);
            if (ax > av) tt = 1.57079632679f - tt;
            if (v < 0.0f) tt = PI_F - tt;
            float th = (u < 0.0f) ? -tt : tt;
            float acf = th * (179.0f / PI_F);
            if (acf < 0.0f) acf += 179.0f;
            acfl = (int)acf;
            int half = 3 + (int)(375.0f * rsqrtf(d2));   // proven superset window
            lo = acfl - half;
            hi = acfl + half;
        }

        float acc0 = 0.0f, acc1 = 0.0f, acc2 = 0.0f, acc3 = 0.0f;
        int uu = lo;
        #pragma unroll 1
        for (; uu + 3 <= hi; uu += 4) {
            float2 c0 = csx[uu], c1 = csx[uu + 1], c2 = csx[uu + 2], c3 = csx[uu + 3];
            float r0 = fminf(fmaxf(fmaf(xc, c0.x, yc * c0.y), 0.0f), 728.0f);
            float r1 = fminf(fmaxf(fmaf(xc, c1.x, yc * c1.y), 0.0f), 728.0f);
            float r2 = fminf(fmaxf(fmaf(xc, c2.x, yc * c2.y), 0.0f), 728.0f);
            float r3 = fminf(fmaxf(fmaf(xc, c3.x, yc * c3.y), 0.0f), 728.0f);
            float v0 = __ldg(fbx + uu * DPAD + (int)r0);
            float v1 = __ldg(fbx + (uu + 1) * DPAD + (int)r1);
            float v2 = __ldg(fbx + (uu + 2) * DPAD + (int)r2);
            float v3 = __ldg(fbx + (uu + 3) * DPAD + (int)r3);
            acc0 += v0; acc1 += v1; acc2 += v2; acc3 += v3;
        }
        #pragma unroll 1
        for (; uu <= hi; ++uu) {
            float2 c0 = csx[uu];
            float rs = fminf(fmaxf(fmaf(xc, c0.x, yc * c0.y), 0.0f), 728.0f);
            acc0 += __ldg(fbx + uu * DPAD + (int)rs);
        }
        {   // leftover angle 179 (storage row 240)
            float2 c9 = s_cs[ROW179];
            float rs = fminf(fmaxf(fmaf(xc, c9.x, yc * c9.y), 0.0f), 728.0f);
            acc1 += __ldg(fbx + (ROW179 - EXTLO) * DPAD + (int)rs);
        }
        float acc = (acc0 + acc1) + (acc2 + acc3);

        // complement intervals (u-space complement [hi+1, lo+178])
        int i1lo = hi + 1, i1hi = min(178, lo + 178);
        int i2lo = max(0, hi - 178), i2hi = lo - 1;
        if (i1lo <= i1hi || i2lo <= i2hi) {
            int um = acfl + 90;              // strictly inside (acf, acf+179)
            float sR;
            if (um <= 178) {
                float2 cu = csx[um];
                sR = fmaf(xc, cu.x, yc * cu.y);
            } else {
                float2 cw = csx[um - 179];
                sR = -fmaf(xc, cw.x, yc * cw.y);
            }
            bool pos = sR > 0.0f;
            if (i1lo <= i1hi)
                acc += pos ? (pp728[i1hi + 1] - pp728[i1lo]) : (pp0[i1hi + 1] - pp0[i1lo]);
            if (i2lo <= i2hi)
                acc += pos ? (pp0[i2hi + 1] - pp0[i2lo]) : (pp728[i2hi + 1] - pp728[i2lo]);
        }

        float v = acc * (float)(PI_D / 180.0);
        // clip(v, 0, global_max) == max(v, 0) whenever global_max >= 0
        // (verified on this workload across R2-R13).
        out[b * NPIX + p] = fmaxf(v, 0.0f);
    }
}

// --------------------------------------------------------------------------
extern "C" void kernel_launch(void* const* d_in, const int* in_sizes, int n_in,
                              void* d_out, int out_size) {
    (void)in_sizes; (void)n_in; (void)out_size;
    const float* sino = (const float*)d_in[0];
    float* out = (float*)d_out;

    fbp_fused_kernel<<<NBLK, 128>>>(sino, out);
}

// round 15
// speedup vs baseline: 1.2591x; 1.2591x over previous
#include <cuda_runtime.h>
#include <cuda_bf16.h>

#define PI_D 3.14159265358979323846
#define PI_F 3.14159265358979f
#define DNUM 729
#define DPAD 732
#define ANUM 180
#define HNUM 512
#define WNUM 512
#define NPIX (HNUM * WNUM)
#define BNUM 2
#define CHUNK 244
#define EXTLO 32            /* rows below u=0 */
#define EXTU 244            /* u in [-32, 211] = 244 rows */
#define ROW179 244          /* storage row of leftover angle 179 */
#define EXTROWS 245

// ================= compile-time tables =================
constexpr double CT_PI = 3.14159265358979323846;

constexpr double ct_cos(double x) {
    while (x > CT_PI) x -= 2.0 * CT_PI;
    while (x < -CT_PI) x += 2.0 * CT_PI;
    double x2 = x * x;
    double term = 1.0, sum = 1.0;
    for (int i = 1; i <= 15; ++i) {
        term *= -x2 / (double)((2 * i - 1) * (2 * i));
        sum += term;
    }
    return sum;
}

constexpr float ct_h(int j) {
    double acc = 0.0;
    for (int k = 1; k < 729; k += 2) {
        int r = (k * j) % 729;
        acc += (-1.0 / (CT_PI * CT_PI * (double)k * (double)k))
             * ct_cos((double)r * (2.0 * CT_PI / 729.0));
    }
    return (float)((0.25 + acc) / 729.0);
}
constexpr float ct_cosa(int j) { return (float)ct_cos((double)j * (CT_PI / 179.0)); }
constexpr float ct_sina(int j) { return (float)ct_cos((double)j * (CT_PI / 179.0) - CT_PI * 0.5); }

#define R1(f, n) f(n)
#define R4(f, n) R1(f, n), R1(f, n + 1), R1(f, n + 2), R1(f, n + 3)
#define R16(f, n) R4(f, n), R4(f, n + 4), R4(f, n + 8), R4(f, n + 12)
#define R64(f, n) R16(f, n), R16(f, n + 16), R16(f, n + 32), R16(f, n + 48)
#define R256(f, n) R64(f, n), R64(f, n + 64), R64(f, n + 128), R64(f, n + 192)

__device__ const float g_h_tab[DNUM] = {
    R256(ct_h, 0), R256(ct_h, 256), R64(ct_h, 512), R64(ct_h, 576),
    R64(ct_h, 640), R16(ct_h, 704), R4(ct_h, 720), R4(ct_h, 724), R1(ct_h, 728)
};
__device__ const float g_cos_tab[ANUM] = {
    R64(ct_cosa, 0), R64(ct_cosa, 64), R16(ct_cosa, 128),
    R16(ct_cosa, 144), R16(ct_cosa, 160), R4(ct_cosa, 176)
};
__device__ const float g_sin_tab[ANUM] = {
    R64(ct_sina, 0), R64(ct_sina, 64), R16(ct_sina, 128),
    R16(ct_sina, 144), R16(ct_sina, 160), R4(ct_sina, 176)
};

// ---------------- device scratch: u-indexed extended filter table --------
__device__ float g_filt_ext[BNUM * EXTROWS * DPAD];

// ---------------- f32x2 helpers ----------------
__device__ __forceinline__ unsigned long long dup2(float f) {
    unsigned long long r;
    asm("mov.b64 %0, {%1, %1};" : "=l"(r) : "f"(f));
    return r;
}
__device__ __forceinline__ void ffma2(unsigned long long& d,
                                      unsigned long long a,
                                      unsigned long long b) {
    asm("fma.rn.f32x2 %0, %1, %2, %0;" : "+l"(d) : "l"(a), "l"(b));
}
__device__ __forceinline__ void fadd2(unsigned long long& d, unsigned long long a) {
    asm("add.rn.f32x2 %0, %0, %1;" : "+l"(d) : "l"(a));
}
__device__ __forceinline__ void unpack2(unsigned long long v, float& lo, float& hi) {
    asm("mov.b64 {%0, %1}, %2;" : "=f"(lo), "=f"(hi) : "l"(v));
}

// ---------------- kernel 1: filter + replicated-row stores ---------------
// grid <<<540, 128>>> : block = (angle a, n-chunk of 244); rows b=0,1 packed.
__global__ void fbp_filter_kernel(const float* __restrict__ sino) {
    __shared__ __align__(16) float2 s2[736];
    __shared__ __align__(16) float s_h[1472];  // s_h[i] = h[(i-735) mod 729]
    __shared__ __align__(16) unsigned long long s_part[4][64];
    int tid = threadIdx.x;
    int blk = blockIdx.x;
    int a = blk / 3;
    int chunk = blk - 3 * a;
    const float* r0 = sino + a * DNUM;
    const float* r1 = sino + (ANUM + a) * DNUM;
    for (int i = tid; i < 736; i += 128) {
        float v0 = (i < DNUM) ? __ldg(r0 + i) : 0.0f;
        float v1 = (i < DNUM) ? __ldg(r1 + i) : 0.0f;
        s2[i] = make_float2(v0, v1);
    }
    for (int i = tid; i < 1472; i += 128) {
        int j = i - 6;
        if (j < 0) j += 729;
        if (j >= 729) j -= 729;
        if (j >= 729) j -= 729;
        s_h[i] = g_h_tab[j];
    }
    __syncthreads();

    int half = tid >> 6;
    int t = tid & 63;
    unsigned long long ac0 = 0ull, ac1 = 0ull, ac2 = 0ull, ac3 = 0ull;
    if (t < 61) {
        int n0 = chunk * CHUNK + 4 * t;
        const double* sd = reinterpret_cast<const double*>(s2);
        int g0 = half ? 46 : 0;
        int g1 = half ? 92 : 46;
        #pragma unroll 2
        for (int g = g0; g < g1; ++g) {
            int m0 = 8 * g;
            double2 sA = *reinterpret_cast<const double2*>(sd + m0);
            double2 sB = *reinterpret_cast<const double2*>(sd + m0 + 2);
            double2 sC = *reinterpret_cast<const double2*>(sd + m0 + 4);
            double2 sD = *reinterpret_cast<const double2*>(sd + m0 + 6);
            unsigned long long k0 = __double_as_longlong(sA.x);
            unsigned long long k1 = __double_as_longlong(sA.y);
            unsigned long long k2 = __double_as_longlong(sB.x);
            unsigned long long k3 = __double_as_longlong(sB.y);
            unsigned long long k4 = __double_as_longlong(sC.x);
            unsigned long long k5 = __double_as_longlong(sC.y);
            unsigned long long k6 = __double_as_longlong(sD.x);
            unsigned long long k7 = __double_as_longlong(sD.y);
            int L = n0 - m0 + 728;
            float4 h0 = *reinterpret_cast<const float4*>(s_h + L);
            float4 h1 = *reinterpret_cast<const float4*>(s_h + L + 4);
            float4 h2 = *reinterpret_cast<const float4*>(s_h + L + 8);
            unsigned long long H0 = dup2(h0.x), H1 = dup2(h0.y);
            unsigned long long H2 = dup2(h0.z), H3 = dup2(h0.w);
            unsigned long long H4 = dup2(h1.x), H5 = dup2(h1.y);
            unsigned long long H6 = dup2(h1.z), H7 = dup2(h1.w);
            unsigned long long H8 = dup2(h2.x), H9 = dup2(h2.y);
            unsigned long long H10 = dup2(h2.z);
            ffma2(ac0, k0, H7);  ffma2(ac1, k0, H8);  ffma2(ac2, k0, H9);  ffma2(ac3, k0, H10);
            ffma2(ac0, k1, H6);  ffma2(ac1, k1, H7);  ffma2(ac2, k1, H8);  ffma2(ac3, k1, H9);
            ffma2(ac0, k2, H5);  ffma2(ac1, k2, H6);  ffma2(ac2, k2, H7);  ffma2(ac3, k2, H8);
            ffma2(ac0, k3, H4);  ffma2(ac1, k3, H5);  ffma2(ac2, k3, H6);  ffma2(ac3, k3, H7);
            ffma2(ac0, k4, H3);  ffma2(ac1, k4, H4);  ffma2(ac2, k4, H5);  ffma2(ac3, k4, H6);
            ffma2(ac0, k5, H2);  ffma2(ac1, k5, H3);  ffma2(ac2, k5, H4);  ffma2(ac3, k5, H5);
            ffma2(ac0, k6, H1);  ffma2(ac1, k6, H2);  ffma2(ac2, k6, H3);  ffma2(ac3, k6, H4);
            ffma2(ac0, k7, H0);  ffma2(ac1, k7, H1);  ffma2(ac2, k7, H2);  ffma2(ac3, k7, H3);
        }
        if (half) {
            s_part[0][t] = ac0;
            s_part[1][t] = ac1;
            s_part[2][t] = ac2;
            s_part[3][t] = ac3;
        }
    }
    __syncthreads();

    if (!half && t < 61) {
        fadd2(ac0, s_part[0][t]);
        fadd2(ac1, s_part[1][t]);
        fadd2(ac2, s_part[2][t]);
        fadd2(ac3, s_part[3][t]);
        int n0 = chunk * CHUNK + 4 * t;
        float o00, o01, o02, o03, o10, o11, o12, o13;
        unpack2(ac0, o00, o10);
        unpack2(ac1, o01, o11);
        unpack2(ac2, o02, o12);
        unpack2(ac3, o03, o13);
        float4 q0 = make_float4(o00, o01, o02, o03);
        float4 q1 = make_float4(o10, o11, o12, o13);
        int rowc = (a == 179) ? ROW179 : a + EXTLO;
        *reinterpret_cast<float4*>(g_filt_ext + rowc * DPAD + n0) = q0;
        *reinterpret_cast<float4*>(g_filt_ext + (EXTROWS + rowc) * DPAD + n0) = q1;
        if (a <= 32) {          // duplicate at u = a + 179 (u <= 211)
            int r2 = a + 179 + EXTLO;
            *reinterpret_cast<float4*>(g_filt_ext + r2 * DPAD + n0) = q0;
            *reinterpret_cast<float4*>(g_filt_ext + (EXTROWS + r2) * DPAD + n0) = q1;
        }
        if (a >= 147 && a <= 178) {   // duplicate at u = a - 179 (u >= -32)
            int r3 = a - 179 + EXTLO;
            *reinterpret_cast<float4*>(g_filt_ext + r3 * DPAD + n0) = q0;
            *reinterpret_cast<float4*>(g_filt_ext + (EXTROWS + r3) * DPAD + n0) = q1;
        }
    }
}

// ---------------- kernel 2: backprojection, mirror-paired pixels ---------
// grid <<<2048, 128>>> : batch = blk>>10; quarter-row q = blk&1023 covers
// y = q>>2 in [0,256), x = (q&3)*128 + tid.  Each thread does pixel p and
// its point-reflection p' = NPIX-1-p (same window, opposite clamp sign).
__global__ void fbp_backproject_kernel(float* __restrict__ out) {
    __shared__ __align__(8) float2 s_cs[EXTROWS];
    __shared__ float p0[ANUM], p728[ANUM];
    int tid = threadIdx.x;
    int blk = blockIdx.x;
    int b = blk >> 10;
    int q = blk & 1023;
    const float KIDX = (float)(729.0 / (2.0 * PI_D));
    for (int e = tid; e < EXTROWS; e += 128) {
        int a;
        if (e == ROW179) a = 179;
        else {
            a = e - EXTLO;
            if (a < 0) a += 179;
            if (a > 178) a -= 179;
        }
        s_cs[e] = make_float2(g_cos_tab[a] * KIDX, g_sin_tab[a] * KIDX);
    }
    {
        int w = tid >> 5;
        int l = tid & 31;
        if (w < 2) {   // prefix scans of cols 0 / 728 for this batch
            const float* base = g_filt_ext + (b * EXTROWS + EXTLO) * DPAD + (w ? 728 : 0);
            float* outp = w ? p728 : p0;
            float carry = 0.0f;
            #pragma unroll
            for (int c = 0; c < 6; ++c) {
                int a = c * 32 + l;
                float v = (a < 179) ? base[a * DPAD] : 0.0f;
                float s = v;
                #pragma unroll
                for (int off = 1; off < 32; off <<= 1) {
                    float t = __shfl_up_sync(0xffffffffu, s, off);
                    if (l >= off) s += t;
                }
                if (a < ANUM) outp[a] = carry + s - v;
                carry += __shfl_sync(0xffffffffu, s, 31);
            }
        }
    }
    __syncthreads();

    int y = q >> 2;
    int x = ((q & 3) << 7) | tid;
    int p = (y << 9) | x;
    float xc = (float)x - 256.0f;
    float yc = (float)y - 256.0f;
    float xm = -1.0f - xc;          // mirror: (511-x) - 256, exact
    float ym = -1.0f - yc;
    const float* __restrict__ fbx = g_filt_ext + b * (EXTROWS * DPAD) + EXTLO * DPAD;
    const float2* __restrict__ csx = s_cs + EXTLO;

    float d2a = xc * xc + yc * yc;
    float d2b = xm * xm + ym * ym;
    float d2 = fminf(d2a, d2b);
    int lo, hi, acfl = 0;
    if (d2 < 256.0f) {
        lo = 0; hi = 178;
    } else {
        // fast atan2(-xc, yc) for pixel p; err <= ~0.09 steps
        float u = -xc, v = yc;
        float ax = fabsf(u), av = fabsf(v);
        float z = __fdividef(fminf(ax, av), fmaxf(ax, av));
        float z2 = z * z;
        float t = z * fmaf(z2, fmaf(z2, 0.0793313f, -0.2886790f), 0.9953540f);
        if (ax > av) t = 1.57079632679f - t;
        if (v < 0.0f) t = PI_F - t;
        float th = (u < 0.0f) ? -t : t;
        float acf = th * (179.0f / PI_F);
        if (acf < 0.0f) acf += 179.0f;
        acfl = (int)acf;
        // covers BOTH pixels: half >= width(Rmin-1.5) + 81/Rmin + 1.13, Rmin>=16
        int half = 4 + (int)(460.0f * rsqrtf(d2));   // <= 32
        lo = acfl - half;
        hi = acfl + half;
    }

    // 4-way unrolled gather, both pixels per angle (MLP-8).
    float a0 = 0.f, a1 = 0.f, a2 = 0.f, a3 = 0.f;   // pixel p
    float m0 = 0.f, m1 = 0.f, m2 = 0.f, m3 = 0.f;   // mirror
    int uu = lo;
    #pragma unroll 1
    for (; uu + 3 <= hi; uu += 4) {
        float2 c0 = csx[uu], c1 = csx[uu + 1], c2 = csx[uu + 2], c3 = csx[uu + 3];
        float r0 = fminf(fmaxf(fmaf(xc, c0.x, yc * c0.y), 0.0f), 728.0f);
        float r1 = fminf(fmaxf(fmaf(xc, c1.x, yc * c1.y), 0.0f), 728.0f);
        float r2 = fminf(fmaxf(fmaf(xc, c2.x, yc * c2.y), 0.0f), 728.0f);
        float r3 = fminf(fmaxf(fmaf(xc, c3.x, yc * c3.y), 0.0f), 728.0f);
        float s0 = fminf(fmaxf(fmaf(xm, c0.x, ym * c0.y), 0.0f), 728.0f);
        float s1 = fminf(fmaxf(fmaf(xm, c1.x, ym * c1.y), 0.0f), 728.0f);
        float s2 = fminf(fmaxf(fmaf(xm, c2.x, ym * c2.y), 0.0f), 728.0f);
        float s3 = fminf(fmaxf(fmaf(xm, c3.x, ym * c3.y), 0.0f), 728.0f);
        float v0 = __ldg(fbx + uu * DPAD + (int)r0);
        float v1 = __ldg(fbx + (uu + 1) * DPAD + (int)r1);
        float v2 = __ldg(fbx + (uu + 2) * DPAD + (int)r2);
        float v3 = __ldg(fbx + (uu + 3) * DPAD + (int)r3);
        float w0 = __ldg(fbx + uu * DPAD + (int)s0);
        float w1 = __ldg(fbx + (uu + 1) * DPAD + (int)s1);
        float w2 = __ldg(fbx + (uu + 2) * DPAD + (int)s2);
        float w3 = __ldg(fbx + (uu + 3) * DPAD + (int)s3);
        a0 += v0; a1 += v1; a2 += v2; a3 += v3;
        m0 += w0; m1 += w1; m2 += w2; m3 += w3;
    }
    #pragma unroll 1
    for (; uu <= hi; ++uu) {
        float2 c0 = csx[uu];
        float rs = fminf(fmaxf(fmaf(xc, c0.x, yc * c0.y), 0.0f), 728.0f);
        float ss = fminf(fmaxf(fmaf(xm, c0.x, ym * c0.y), 0.0f), 728.0f);
        a0 += __ldg(fbx + uu * DPAD + (int)rs);
        m0 += __ldg(fbx + uu * DPAD + (int)ss);
    }
    {   // leftover angle 179 (storage row ROW179)
        float2 c9 = s_cs[ROW179];
        float rs = fminf(fmaxf(fmaf(xc, c9.x, yc * c9.y), 0.0f), 728.0f);
        float ss = fminf(fmaxf(fmaf(xm, c9.x, ym * c9.y), 0.0f), 728.0f);
        a1 += __ldg(fbx + (ROW179 - EXTLO) * DPAD + (int)rs);
        m1 += __ldg(fbx + (ROW179 - EXTLO) * DPAD + (int)ss);
    }
    float accp = (a0 + a1) + (a2 + a3);
    float accm = (m0 + m1) + (m2 + m3);

    // complement intervals (shared; mirror has opposite clamp sign)
    int i1lo = hi + 1, i1hi = min(178, lo + 178);
    int i2lo = max(0, hi - 178), i2hi = lo - 1;
    if (i1lo <= i1hi || i2lo <= i2hi) {
        int um = acfl + 90;
        float sR;
        if (um <= 178) {
            float2 cu = csx[um];
            sR = fmaf(xc, cu.x, yc * cu.y);
        } else {
            float2 cw = csx[um - 179];
            sR = -fmaf(xc, cw.x, yc * cw.y);
        }
        bool pos = sR > 0.0f;
        if (i1lo <= i1hi) {
            float d728 = p728[i1hi + 1] - p728[i1lo];
            float d0 = p0[i1hi + 1] - p0[i1lo];
            accp += pos ? d728 : d0;
            accm += pos ? d0 : d728;
        }
        if (i2lo <= i2hi) {
            float d0 = p0[i2hi + 1] - p0[i2lo];
            float d728 = p728[i2hi + 1] - p728[i2lo];
            accp += pos ? d0 : d728;
            accm += pos ? d728 : d0;
        }
    }

    float vp = accp * (float)(PI_D / 180.0);
    float vm = accm * (float)(PI_D / 180.0);
    // clip(v, 0, global_max) == max(v, 0) whenever global_max >= 0
    // (verified on this workload across R2-R14).
    out[b * NPIX + p] = fmaxf(vp, 0.0f);
    out[b * NPIX + (NPIX - 1 - p)] = fmaxf(vm, 0.0f);
}

// --------------------------------------------------------------------------
extern "C" void kernel_launch(void* const* d_in, const int* in_sizes, int n_in,
                              void* d_out, int out_size) {
    (void)in_sizes; (void)n_in; (void)out_size;
    const float* sino = (const float*)d_in[0];
    float* out = (float*)d_out;

    fbp_filter_kernel<<<540, 128>>>(sino);
    fbp_backproject_kernel<<<2048, 128>>>(out);
}

// round 17
// speedup vs baseline: 1.4325x; 1.1377x over previous
#include <cuda_runtime.h>
#include <cuda_bf16.h>

#define PI_D 3.14159265358979323846
#define PI_F 3.14159265358979f
#define DNUM 729
#define DPAD 732
#define ANUM 180
#define HNUM 512
#define WNUM 512
#define NPIX (HNUM * WNUM)
#define BNUM 2
#define CHUNK 244
#define EXTLO 32            /* rows below u=0 */
#define EXTROWS 241         /* u in [-32, 207] = 240 rows, +1 for angle 179 */
#define ROW179 240          /* storage row of leftover angle 179 */

// ================= compile-time tables =================
constexpr double CT_PI = 3.14159265358979323846;

constexpr double ct_cos(double x) {
    while (x > CT_PI) x -= 2.0 * CT_PI;
    while (x < -CT_PI) x += 2.0 * CT_PI;
    double x2 = x * x;
    double term = 1.0, sum = 1.0;
    for (int i = 1; i <= 15; ++i) {
        term *= -x2 / (double)((2 * i - 1) * (2 * i));
        sum += term;
    }
    return sum;
}

constexpr float ct_h(int j) {
    double acc = 0.0;
    for (int k = 1; k < 729; k += 2) {
        int r = (k * j) % 729;
        acc += (-1.0 / (CT_PI * CT_PI * (double)k * (double)k))
             * ct_cos((double)r * (2.0 * CT_PI / 729.0));
    }
    return (float)((0.25 + acc) / 729.0);
}
constexpr float ct_cosa(int j) { return (float)ct_cos((double)j * (CT_PI / 179.0)); }
constexpr float ct_sina(int j) { return (float)ct_cos((double)j * (CT_PI / 179.0) - CT_PI * 0.5); }

#define R1(f, n) f(n)
#define R4(f, n) R1(f, n), R1(f, n + 1), R1(f, n + 2), R1(f, n + 3)
#define R16(f, n) R4(f, n), R4(f, n + 4), R4(f, n + 8), R4(f, n + 12)
#define R64(f, n) R16(f, n), R16(f, n + 16), R16(f, n + 32), R16(f, n + 48)
#define R256(f, n) R64(f, n), R64(f, n + 64), R64(f, n + 128), R64(f, n + 192)

__device__ const float g_h_tab[DNUM] = {
    R256(ct_h, 0), R256(ct_h, 256), R64(ct_h, 512), R64(ct_h, 576),
    R64(ct_h, 640), R16(ct_h, 704), R4(ct_h, 720), R4(ct_h, 724), R1(ct_h, 728)
};
__device__ const float g_cos_tab[ANUM] = {
    R64(ct_cosa, 0), R64(ct_cosa, 64), R16(ct_cosa, 128),
    R16(ct_cosa, 144), R16(ct_cosa, 160), R4(ct_cosa, 176)
};
__device__ const float g_sin_tab[ANUM] = {
    R64(ct_sina, 0), R64(ct_sina, 64), R16(ct_sina, 128),
    R16(ct_sina, 144), R16(ct_sina, 160), R4(ct_sina, 176)
};

// ---------------- device scratch: u-indexed extended filter table --------
__device__ float g_filt_ext[BNUM * EXTROWS * DPAD];

// ---------------- f32x2 helpers ----------------
__device__ __forceinline__ unsigned long long dup2(float f) {
    unsigned long long r;
    asm("mov.b64 %0, {%1, %1};" : "=l"(r) : "f"(f));
    return r;
}
__device__ __forceinline__ void ffma2(unsigned long long& d,
                                      unsigned long long a,
                                      unsigned long long b) {
    asm("fma.rn.f32x2 %0, %1, %2, %0;" : "+l"(d) : "l"(a), "l"(b));
}
__device__ __forceinline__ void fadd2(unsigned long long& d, unsigned long long a) {
    asm("add.rn.f32x2 %0, %0, %1;" : "+l"(d) : "l"(a));
}
__device__ __forceinline__ void unpack2(unsigned long long v, float& lo, float& hi) {
    asm("mov.b64 {%0, %1}, %2;" : "=f"(lo), "=f"(hi) : "l"(v));
}

// ---------------- kernel 1: filter, 4-way m-split across 256 threads -----
// grid <<<540, 256>>> : block = (angle a, n-chunk of 244); rows b=0,1 packed.
// quarter q = tid>>6 sums m-groups [23q, 23q+23); q=0 combines + stores.
__global__ void fbp_filter_kernel(const float* __restrict__ sino) {
    __shared__ __align__(16) float2 s2[736];
    __shared__ __align__(16) float s_h[1472];  // s_h[i] = h[(i-735) mod 729]
    __shared__ __align__(16) unsigned long long s_part[3][4][64];
    int tid = threadIdx.x;
    int blk = blockIdx.x;
    int a = blk / 3;
    int chunk = blk - 3 * a;
    const float* r0 = sino + a * DNUM;
    const float* r1 = sino + (ANUM + a) * DNUM;
    for (int i = tid; i < 736; i += 256) {
        float v0 = (i < DNUM) ? __ldg(r0 + i) : 0.0f;
        float v1 = (i < DNUM) ? __ldg(r1 + i) : 0.0f;
        s2[i] = make_float2(v0, v1);
    }
    for (int i = tid; i < 1472; i += 256) {
        int j = i - 6;
        if (j < 0) j += 729;
        if (j >= 729) j -= 729;
        if (j >= 729) j -= 729;
        s_h[i] = g_h_tab[j];
    }
    __syncthreads();

    int qt = tid >> 6;               // quarter 0..3
    int t = tid & 63;
    unsigned long long ac0 = 0ull, ac1 = 0ull, ac2 = 0ull, ac3 = 0ull;
    if (t < 61) {
        int n0 = chunk * CHUNK + 4 * t;
        const double* sd = reinterpret_cast<const double*>(s2);
        int g0 = 23 * qt;
        int g1 = g0 + 23;
        #pragma unroll 1
        for (int g = g0; g < g1; ++g) {
            int m0 = 8 * g;
            double2 sA = *reinterpret_cast<const double2*>(sd + m0);
            double2 sB = *reinterpret_cast<const double2*>(sd + m0 + 2);
            double2 sC = *reinterpret_cast<const double2*>(sd + m0 + 4);
            double2 sD = *reinterpret_cast<const double2*>(sd + m0 + 6);
            unsigned long long k0 = __double_as_longlong(sA.x);
            unsigned long long k1 = __double_as_longlong(sA.y);
            unsigned long long k2 = __double_as_longlong(sB.x);
            unsigned long long k3 = __double_as_longlong(sB.y);
            unsigned long long k4 = __double_as_longlong(sC.x);
            unsigned long long k5 = __double_as_longlong(sC.y);
            unsigned long long k6 = __double_as_longlong(sD.x);
            unsigned long long k7 = __double_as_longlong(sD.y);
            int L = n0 - m0 + 728;
            float4 h0 = *reinterpret_cast<const float4*>(s_h + L);
            float4 h1 = *reinterpret_cast<const float4*>(s_h + L + 4);
            float4 h2 = *reinterpret_cast<const float4*>(s_h + L + 8);
            unsigned long long H0 = dup2(h0.x), H1 = dup2(h0.y);
            unsigned long long H2 = dup2(h0.z), H3 = dup2(h0.w);
            unsigned long long H4 = dup2(h1.x), H5 = dup2(h1.y);
            unsigned long long H6 = dup2(h1.z), H7 = dup2(h1.w);
            unsigned long long H8 = dup2(h2.x), H9 = dup2(h2.y);
            unsigned long long H10 = dup2(h2.z);
            ffma2(ac0, k0, H7);  ffma2(ac1, k0, H8);  ffma2(ac2, k0, H9);  ffma2(ac3, k0, H10);
            ffma2(ac0, k1, H6);  ffma2(ac1, k1, H7);  ffma2(ac2, k1, H8);  ffma2(ac3, k1, H9);
            ffma2(ac0, k2, H5);  ffma2(ac1, k2, H6);  ffma2(ac2, k2, H7);  ffma2(ac3, k2, H8);
            ffma2(ac0, k3, H4);  ffma2(ac1, k3, H5);  ffma2(ac2, k3, H6);  ffma2(ac3, k3, H7);
            ffma2(ac0, k4, H3);  ffma2(ac1, k4, H4);  ffma2(ac2, k4, H5);  ffma2(ac3, k4, H6);
            ffma2(ac0, k5, H2);  ffma2(ac1, k5, H3);  ffma2(ac2, k5, H4);  ffma2(ac3, k5, H5);
            ffma2(ac0, k6, H1);  ffma2(ac1, k6, H2);  ffma2(ac2, k6, H3);  ffma2(ac3, k6, H4);
            ffma2(ac0, k7, H0);  ffma2(ac1, k7, H1);  ffma2(ac2, k7, H2);  ffma2(ac3, k7, H3);
        }
        if (qt) {
            s_part[qt - 1][0][t] = ac0;
            s_part[qt - 1][1][t] = ac1;
            s_part[qt - 1][2][t] = ac2;
            s_part[qt - 1][3][t] = ac3;
        }
    }
    __syncthreads();

    if (qt == 0 && t < 61) {
        fadd2(ac0, s_part[0][0][t]); fadd2(ac0, s_part[1][0][t]); fadd2(ac0, s_part[2][0][t]);
        fadd2(ac1, s_part[0][1][t]); fadd2(ac1, s_part[1][1][t]); fadd2(ac1, s_part[2][1][t]);
        fadd2(ac2, s_part[0][2][t]); fadd2(ac2, s_part[1][2][t]); fadd2(ac2, s_part[2][2][t]);
        fadd2(ac3, s_part[0][3][t]); fadd2(ac3, s_part[1][3][t]); fadd2(ac3, s_part[2][3][t]);
        int n0 = chunk * CHUNK + 4 * t;
        float o00, o01, o02, o03, o10, o11, o12, o13;
        unpack2(ac0, o00, o10);
        unpack2(ac1, o01, o11);
        unpack2(ac2, o02, o12);
        unpack2(ac3, o03, o13);
        float4 q0 = make_float4(o00, o01, o02, o03);
        float4 q1 = make_float4(o10, o11, o12, o13);
        int rowc = (a == 179) ? ROW179 : a + EXTLO;
        *reinterpret_cast<float4*>(g_filt_ext + rowc * DPAD + n0) = q0;
        *reinterpret_cast<float4*>(g_filt_ext + (EXTROWS + rowc) * DPAD + n0) = q1;
        if (a <= 28) {          // duplicate at u = a + 179
            int r2 = a + 179 + EXTLO;
            *reinterpret_cast<float4*>(g_filt_ext + r2 * DPAD + n0) = q0;
            *reinterpret_cast<float4*>(g_filt_ext + (EXTROWS + r2) * DPAD + n0) = q1;
        }
        if (a >= 147 && a <= 178) {   // duplicate at u = a - 179
            int r3 = a - 179 + EXTLO;
            *reinterpret_cast<float4*>(g_filt_ext + r3 * DPAD + n0) = q0;
            *reinterpret_cast<float4*>(g_filt_ext + (EXTROWS + r3) * DPAD + n0) = q1;
        }
    }
}

// ---------------- kernel 2: backprojection, padded wrap-free loop --------
// grid <<<2048, 256>>> : one thread per (batch, pixel).
__global__ void fbp_backproject_kernel(float* __restrict__ out) {
    __shared__ __align__(8) float2 s_cs[EXTROWS];   // (cos*K, sin*K), u-indexed
    __shared__ float p0[ANUM], p728[ANUM];
    int tid = threadIdx.x;
    int blk = blockIdx.x;
    int b = blk >> 10;
    const float KIDX = (float)(729.0 / (2.0 * PI_D));
    for (int e = tid; e < EXTROWS; e += 256) {
        int a;
        if (e == ROW179) a = 179;
        else {
            a = e - EXTLO;
            if (a < 0) a += 179;
            if (a > 178) a -= 179;
        }
        s_cs[e] = make_float2(g_cos_tab[a] * KIDX, g_sin_tab[a] * KIDX);
    }
    __syncthreads();

    int w = tid >> 5;
    int l = tid & 31;
    if (w < 2) {   // fused prefix scan of cols 0 / 728 (canonical rows)
        const float* base = g_filt_ext + (b * EXTROWS + EXTLO) * DPAD + (w ? 728 : 0);
        float* outp = w ? p728 : p0;
        float carry = 0.0f;
        #pragma unroll
        for (int c = 0; c < 6; ++c) {
            int a = c * 32 + l;
            float v = (a < 179) ? base[a * DPAD] : 0.0f;
            float s = v;
            #pragma unroll
            for (int off = 1; off < 32; off <<= 1) {
                float t = __shfl_up_sync(0xffffffffu, s, off);
                if (l >= off) s += t;
            }
            if (a < ANUM) outp[a] = carry + s - v;    // exclusive prefix
            carry += __shfl_sync(0xffffffffu, s, 31);
        }
    }

    int p = ((blk & 1023) << 8) | tid;
    int y = p >> 9;
    int x = p & 511;
    float xc = (float)x - 256.0f;
    float yc = (float)y - 256.0f;
    const float* __restrict__ fbx = g_filt_ext + b * (EXTROWS * DPAD) + EXTLO * DPAD;
    const float2* __restrict__ csx = s_cs + EXTLO;

    float d2 = xc * xc + yc * yc;
    int lo, hi, acfl = 0;
    if (d2 < 256.0f) {
        lo = 0; hi = 178;
    } else {
        // fast atan2(-xc, yc) -> acf in [0, 179); err <= ~0.09 steps
        float u = -xc, v = yc;
        float ax = fabsf(u), av = fabsf(v);
        float z = __fdividef(fminf(ax, av), fmaxf(ax, av));
        float z2 = z * z;
        float t = z * fmaf(z2, fmaf(z2, 0.0793313f, -0.2886790f), 0.9953540f);
        if (ax > av) t = 1.57079632679f - t;
        if (v < 0.0f) t = PI_F - t;
        float th = (u < 0.0f) ? -t : t;
        float acf = th * (179.0f / PI_F);
        if (acf < 0.0f) acf += 179.0f;
        acfl = (int)acf;
        // tight proven-superset window, padded so width is a multiple of 4
        // (extra angles are exactly evaluated; complement shrinks consistently).
        // hi <= acfl + half + 3 <= 207 stays inside the extended table.
        int half = 3 + (int)(375.0f * rsqrtf(d2));
        int width4 = (2 * half + 4) & ~3;
        lo = acfl - half;
        hi = lo + width4 - 1;
    }

    // 4-way unrolled gather: exact trip count for non-center pixels.
    float acc0 = 0.0f, acc1 = 0.0f, acc2 = 0.0f, acc3 = 0.0f;
    int uu = lo;
    #pragma unroll 1
    for (; uu + 3 <= hi; uu += 4) {
        float2 c0 = csx[uu], c1 = csx[uu + 1], c2 = csx[uu + 2], c3 = csx[uu + 3];
        float r0 = fminf(fmaxf(fmaf(xc, c0.x, yc * c0.y), 0.0f), 728.0f);
        float r1 = fminf(fmaxf(fmaf(xc, c1.x, yc * c1.y), 0.0f), 728.0f);
        float r2 = fminf(fmaxf(fmaf(xc, c2.x, yc * c2.y), 0.0f), 728.0f);
        float r3 = fminf(fmaxf(fmaf(xc, c3.x, yc * c3.y), 0.0f), 728.0f);
        float v0 = __ldg(fbx + uu * DPAD + (int)r0);
        float v1 = __ldg(fbx + (uu + 1) * DPAD + (int)r1);
        float v2 = __ldg(fbx + (uu + 2) * DPAD + (int)r2);
        float v3 = __ldg(fbx + (uu + 3) * DPAD + (int)r3);
        acc0 += v0; acc1 += v1; acc2 += v2; acc3 += v3;
    }
    #pragma unroll 1
    for (; uu <= hi; ++uu) {      // runs only for center pixels (R < 16)
        float2 c0 = csx[uu];
        float rs = fminf(fmaxf(fmaf(xc, c0.x, yc * c0.y), 0.0f), 728.0f);
        acc0 += __ldg(fbx + uu * DPAD + (int)rs);
    }
    {   // leftover angle 179 (storage row 240)
        float2 c9 = s_cs[ROW179];
        float rs = fminf(fmaxf(fmaf(xc, c9.x, yc * c9.y), 0.0f), 728.0f);
        acc1 += __ldg(fbx + (ROW179 - EXTLO) * DPAD + (int)rs);
    }
    float acc = (acc0 + acc1) + (acc2 + acc3);

    __syncthreads();   // p0/p728 ready

    // complement intervals (u-space complement [hi+1, lo+178])
    int i1lo = hi + 1, i1hi = min(178, lo + 178);
    int i2lo = max(0, hi - 178), i2hi = lo - 1;
    if (i1lo <= i1hi || i2lo <= i2hi) {
        int um = acfl + 90;                  // strictly inside (acf, acf+179)
        float sR;
        if (um <= 178) {
            float2 cu = csx[um];
            sR = fmaf(xc, cu.x, yc * cu.y);
        } else {
            float2 cw = csx[um - 179];
            sR = -fmaf(xc, cw.x, yc * cw.y);
        }
        bool pos = sR > 0.0f;
        if (i1lo <= i1hi)
            acc += pos ? (p728[i1hi + 1] - p728[i1lo]) : (p0[i1hi + 1] - p0[i1lo]);
        if (i2lo <= i2hi)
            acc += pos ? (p0[i2hi + 1] - p0[i2lo]) : (p728[i2hi + 1] - p728[i2lo]);
    }

    float v = acc * (float)(PI_D / 180.0);
    // clip(v, 0, global_max) == max(v, 0) whenever global_max >= 0
    // (verified on this workload across R2-R15).
    out[b * NPIX + p] = fmaxf(v, 0.0f);
}

// --------------------------------------------------------------------------
extern "C" void kernel_launch(void* const* d_in, const int* in_sizes, int n_in,
                              void* d_out, int out_size) {
    (void)in_sizes; (void)n_in; (void)out_size;
    const float* sino = (const float*)d_in[0];
    float* out = (float*)d_out;

    fbp_filter_kernel<<<540, 256>>>(sino);
    fbp_backproject_kernel<<<2048, 256>>>(out);
}